// round 17
// baseline (speedup 1.0000x reference)
#include <cuda_runtime.h>

#define T_STEPS 1000
#define B_TOT   256
#define FIN     39
#define H       100
#define NCLS    20
#define CH      28          // rec chunk floats
#define HP      112         // padded h floats per batch
#define RING    4

// dynamic smem layout (bytes)
#define OFF_W    0                       // W_ih table: 300 rows x 176B (44 words)
#define W_BYTES  (300 * 176)             // 52800
#define OFF_GI   (OFF_W + W_BYTES)       // gi ring: RING x 600 floats
#define GI_BYTES (RING * 600 * 4)        // 9600
#define OFF_X    (OFF_GI + GI_BYTES)     // x ring: RING x 2 x 40 floats
#define X_BYTES  (RING * 2 * 40 * 4)     // 1280
#define OFF_H    (OFF_X + X_BYTES)       // h: 2 x 2 x HP floats
#define H_BYTES  (2 * 2 * HP * 4)        // 1792
#define OFF_FEAT (OFF_H + H_BYTES)       // feat: 2 x 200 floats
#define FEAT_BYTES (2 * 2 * H * 4)       // 1600
#define SMEM_TOTAL (OFF_FEAT + FEAT_BYTES)   // 67072

typedef unsigned long long u64;

__device__ __forceinline__ u64 pk(float x, float y) {
    u64 r; asm("mov.b64 %0,{%1,%2};" : "=l"(r) : "f"(x), "f"(y)); return r;
}
__device__ __forceinline__ void fma2(u64 &d, u64 a, u64 b) {
    asm("fma.rn.f32x2 %0,%1,%2,%0;" : "+l"(d) : "l"(a), "l"(b));
}
__device__ __forceinline__ u64 add2(u64 a, u64 b) {
    u64 r; asm("add.rn.f32x2 %0,%1,%2;" : "=l"(r) : "l"(a), "l"(b)); return r;
}
__device__ __forceinline__ float hsum2(u64 a) {
    float x, y; asm("mov.b64 {%0,%1},%2;" : "=f"(x), "=f"(y) : "l"(a)); return x + y;
}
__device__ __forceinline__ void lds_v2u64(u64 &a, u64 &b, unsigned addr) {
    asm volatile("ld.shared.v2.u64 {%0,%1},[%2];" : "=l"(a), "=l"(b) : "r"(addr));
}
__device__ __forceinline__ float sigf(float x) {
    return __fdividef(1.0f, 1.0f + __expf(-x));
}
__device__ __forceinline__ float tanh_acc(float x) {
    return 2.0f * sigf(2.0f * x) - 1.0f;
}

// ---------------------------------------------------------------------------
// ONE kernel, 128 CTAs x 512 threads.
//   threads 0..399  : R3 recurrent GRU (h = tid>>2, chunk c = tid&3)
//   threads 400..511: helpers. pid<100 produce gi(t+2) for this CTA's 2
//     batches (gates 3pid..3pid+2) into a 4-slot smem gi ring, reading x from
//     a smem x ring (broadcast) and W_ih from a 176B-padded smem table.
//     pid<78 additionally stage one x(t+4) element per step.
// All roles share the single per-step __syncthreads. gi(t+2) written at step
// t is read at step t+2 (2 barriers apart); x slot (t+4)&3 was consumed at
// step t-2. No global scratch, no flags, no cross-CTA sync.
// ---------------------------------------------------------------------------
__global__ void __launch_bounds__(512, 1) gru_onekernel(
    const float* __restrict__ mfcc0, const float* __restrict__ mfcc1,
    const float* __restrict__ mfcc2, const float* __restrict__ len0,
    const float* __restrict__ W_ih, const float* __restrict__ W_hh,
    const float* __restrict__ b_ih, const float* __restrict__ b_hh,
    const float* __restrict__ W_out, const float* __restrict__ b_out,
    float* __restrict__ out)
{
    extern __shared__ __align__(16) unsigned char smem[];
    float* w_tab  = (float*)(smem + OFF_W);     // [300][44], [g][39]=b_ih[g]
    float* gi_rg  = (float*)(smem + OFF_GI);    // [RING][600] : [slot][g*2+b]
    float* x_rg   = (float*)(smem + OFF_X);     // [RING][2][40], [..][39]=1.0
    float* h_shf  = (float*)(smem + OFF_H);     // [2][2][HP]
    float* feat   = (float*)(smem + OFF_FEAT);  // [2][200]

    const int tid = threadIdx.x;
    const int b0  = blockIdx.x * 2;

    // ---- init: W_ih table (bias folded at k=39), h zeros, x pads ----
    for (int i = tid; i < 300 * 44; i += 512) {
        int g = i / 44, k = i - g * 44;
        w_tab[i] = (k < FIN) ? W_ih[g * FIN + k] : ((k == FIN) ? b_ih[g] : 0.0f);
    }
    for (int i = tid; i < 2 * 2 * HP; i += 512) h_shf[i] = 0.0f;
    if (tid < RING * 2) x_rg[tid * 40 + 39] = 1.0f;

    // stage x(0), x(1)
    for (int i = tid; i < 2 * 2 * FIN; i += 512) {
        int tt = i / (2 * FIN), r = i - tt * 2 * FIN;
        int bb = r / FIN, kk = r - bb * FIN;
        const float* s = (kk < 13) ? mfcc0 : (kk < 26) ? mfcc1 : mfcc2;
        int f = (kk < 13) ? kk : (kk < 26) ? (kk - 13) : (kk - 26);
        x_rg[(tt * 2 + bb) * 40 + kk] = s[((size_t)tt * B_TOT + b0 + bb) * 13 + f];
    }

    // ---- role setup ----
    const bool is_rec = (tid < 400);
    const int  h = is_rec ? (tid >> 2) : 0;
    const int  c = tid & 3;
    const unsigned smask = (tid < 384) ? 0xFFFFFFFFu : 0x0000FFFFu;
    const bool fin = is_rec && (c < 2);

    u64 w[3][CH / 2];
    float bh0 = 0.0f, bh1 = 0.0f, bh2 = 0.0f;
    if (is_rec) {
        const int k0   = c * CH;
        const int kcnt = (k0 + CH <= H) ? CH : (H - k0);
        #pragma unroll
        for (int i = 0; i < 3; i++) {
            const float* wr = W_hh + (h + i * H) * H + k0;
            #pragma unroll
            for (int j = 0; j < CH / 2; j++) {
                float x0 = (2 * j     < kcnt) ? wr[2 * j]     : 0.0f;
                float x1 = (2 * j + 1 < kcnt) ? wr[2 * j + 1] : 0.0f;
                w[i][j] = pk(x0, x1);
            }
        }
        if (fin) { bh0 = b_hh[h]; bh1 = b_hh[h + H]; bh2 = b_hh[h + 2 * H]; }
    }

    const int pid   = tid - 400;                 // helpers: 0..111
    const bool isp  = (pid >= 0 && pid < 100);   // gate producers
    const bool isl  = (pid >= 0 && pid < 2 * FIN);  // x loaders (78)
    const float* lsrc = mfcc0;
    int lb = 0, lk = 0;
    if (isl) {
        lb = pid / FIN; lk = pid - lb * FIN;
        const float* s = (lk < 13) ? mfcc0 : (lk < 26) ? mfcc1 : mfcc2;
        int f = (lk < 13) ? lk : (lk < 26) ? (lk - 13) : (lk - 26);
        lsrc = s + (size_t)(b0 + lb) * 13 + f;   // t=0; +t*B_TOT*13 per t
    }

    const unsigned wB  = (unsigned)__cvta_generic_to_shared(w_tab);
    const unsigned xrB = (unsigned)__cvta_generic_to_shared(x_rg);
    const unsigned hB  = (unsigned)__cvta_generic_to_shared(h_shf) + c * (CH * 4);

    __syncthreads();

    // ---- prologue: produce gi(0), gi(1); stage x(2), x(3) ----
    for (int pt = 0; pt < 2; pt++) {
        if (isp) {
            const unsigned xa0 = xrB + (unsigned)(pt * 320);
            u64 xa[20], xb[20];
            #pragma unroll
            for (int j = 0; j < 10; j++) lds_v2u64(xa[2 * j], xa[2 * j + 1], xa0 + j * 16);
            #pragma unroll
            for (int j = 0; j < 10; j++) lds_v2u64(xb[2 * j], xb[2 * j + 1], xa0 + 160 + j * 16);
            #pragma unroll
            for (int i = 0; i < 3; i++) {
                int g = 3 * pid + i;
                unsigned wa = wB + (unsigned)(g * 176);
                u64 a0 = 0, a1 = 0, c0 = 0, c1 = 0;
                #pragma unroll
                for (int j = 0; j < 10; j++) {
                    u64 w0, w1; lds_v2u64(w0, w1, wa + j * 16);
                    fma2(a0, w0, xa[2 * j]); fma2(a1, w1, xa[2 * j + 1]);
                    fma2(c0, w0, xb[2 * j]); fma2(c1, w1, xb[2 * j + 1]);
                }
                gi_rg[pt * 600 + g * 2]     = hsum2(add2(a0, a1));
                gi_rg[pt * 600 + g * 2 + 1] = hsum2(add2(c0, c1));
            }
        }
        if (isl)
            x_rg[((pt + 2) * 2 + lb) * 40 + lk] =
                __ldg(lsrc + (size_t)(pt + 2) * B_TOT * 13);
        __syncthreads();
    }

    // ---- main loop ----
    float hprev = 0.0f, hs = 0.0f, hm = -1e30f;
    int bp = 0;

    for (int t = 0; t < T_STEPS; t++) {
        const int slot = t & 3;

        // x loader: issue LDG for x(t+4) early
        float xr = 0.0f;
        const bool doL = isl && (t + 4 < T_STEPS);
        if (doL) xr = __ldg(lsrc + (size_t)(t + 4) * B_TOT * 13);

        if (is_rec) {
            // gi for this step from the ring (written at t-2)
            float gv0 = 0.0f, gv1 = 0.0f, gv2 = 0.0f;
            if (fin) {
                gv0 = gi_rg[slot * 600 + h * 2 + c];
                gv1 = gi_rg[slot * 600 + (H + h) * 2 + c];
                gv2 = gi_rg[slot * 600 + (2 * H + h) * 2 + c];
            }

            u64 a00 = 0, a01 = 0, a10 = 0, a11 = 0, a20 = 0, a21 = 0;
            u64 d00 = 0, d01 = 0, d10 = 0, d11 = 0, d20 = 0, d21 = 0;
            {
                const unsigned ad = hB + bp * (2 * HP * 4);
                #pragma unroll
                for (int j = 0; j < CH / 4; j++) {
                    u64 q0, q1, r0, r1;
                    lds_v2u64(q0, q1, ad + j * 16);
                    lds_v2u64(r0, r1, ad + HP * 4 + j * 16);
                    fma2(a00, w[0][2 * j], q0); fma2(a01, w[0][2 * j + 1], q1);
                    fma2(a10, w[1][2 * j], q0); fma2(a11, w[1][2 * j + 1], q1);
                    fma2(a20, w[2][2 * j], q0); fma2(a21, w[2][2 * j + 1], q1);
                    fma2(d00, w[0][2 * j], r0); fma2(d01, w[0][2 * j + 1], r1);
                    fma2(d10, w[1][2 * j], r0); fma2(d11, w[1][2 * j + 1], r1);
                    fma2(d20, w[2][2 * j], r0); fma2(d21, w[2][2 * j + 1], r1);
                }
            }
            float s0b0 = hsum2(add2(a00, a01));
            float s1b0 = hsum2(add2(a10, a11));
            float s2b0 = hsum2(add2(a20, a21));
            float s0b1 = hsum2(add2(d00, d01));
            float s1b1 = hsum2(add2(d10, d11));
            float s2b1 = hsum2(add2(d20, d21));

            s0b0 += __shfl_xor_sync(smask, s0b0, 1); s0b0 += __shfl_xor_sync(smask, s0b0, 2);
            s1b0 += __shfl_xor_sync(smask, s1b0, 1); s1b0 += __shfl_xor_sync(smask, s1b0, 2);
            s2b0 += __shfl_xor_sync(smask, s2b0, 1); s2b0 += __shfl_xor_sync(smask, s2b0, 2);
            s0b1 += __shfl_xor_sync(smask, s0b1, 1); s0b1 += __shfl_xor_sync(smask, s0b1, 2);
            s1b1 += __shfl_xor_sync(smask, s1b1, 1); s1b1 += __shfl_xor_sync(smask, s1b1, 2);
            s2b1 += __shfl_xor_sync(smask, s2b1, 1); s2b1 += __shfl_xor_sync(smask, s2b1, 2);

            if (fin) {
                float hr = (c == 0) ? s0b0 : s0b1;
                float hz = (c == 0) ? s1b0 : s1b1;
                float hn = (c == 0) ? s2b0 : s2b1;
                float r = sigf(gv0 + hr + bh0);
                float z = sigf(gv1 + hz + bh1);
                float n = tanh_acc(gv2 + r * (hn + bh2));
                float hnew = n + z * (hprev - n);
                hprev = hnew;
                hs += hnew;
                hm = fmaxf(hm, hnew);
                h_shf[(1 - bp) * (2 * HP) + c * HP + h] = hnew;
            }
        } else if (isp && t + 2 < T_STEPS) {
            // produce gi(t+2) into ring slot (t+2)&3
            const int ps = (t + 2) & 3;
            const unsigned xa0 = xrB + (unsigned)(ps * 320);
            u64 xa[20], xb[20];
            #pragma unroll
            for (int j = 0; j < 10; j++) lds_v2u64(xa[2 * j], xa[2 * j + 1], xa0 + j * 16);
            #pragma unroll
            for (int j = 0; j < 10; j++) lds_v2u64(xb[2 * j], xb[2 * j + 1], xa0 + 160 + j * 16);
            #pragma unroll
            for (int i = 0; i < 3; i++) {
                int g = 3 * pid + i;
                unsigned wa = wB + (unsigned)(g * 176);
                u64 a0 = 0, a1 = 0, c0 = 0, c1 = 0;
                #pragma unroll
                for (int j = 0; j < 10; j++) {
                    u64 w0, w1; lds_v2u64(w0, w1, wa + j * 16);
                    fma2(a0, w0, xa[2 * j]); fma2(a1, w1, xa[2 * j + 1]);
                    fma2(c0, w0, xb[2 * j]); fma2(c1, w1, xb[2 * j + 1]);
                }
                gi_rg[ps * 600 + g * 2]     = hsum2(add2(a0, a1));
                gi_rg[ps * 600 + g * 2 + 1] = hsum2(add2(c0, c1));
            }
        }

        // publish x(t+4) into slot (t+4)&3 (consumed by producer at t+2... freed at t-2)
        if (doL) x_rg[(((t + 4) & 3) * 2 + lb) * 40 + lk] = xr;

        __syncthreads();
        bp ^= 1;
    }

    // ---- pooling + output ----
    if (fin) {
        float inv = 1.0f / len0[b0 + c];
        feat[c * 2 * H + h]     = hs * inv;
        feat[c * 2 * H + H + h] = hm;
    }
    __syncthreads();

    if (tid < 2 * NCLS) {
        int bb = tid / NCLS, cc = tid % NCLS;
        const float* wr = W_out + cc * 2 * H;
        float acc = b_out[cc];
        #pragma unroll 4
        for (int j = 0; j < 2 * H; j++) acc += feat[bb * 2 * H + j] * wr[j];
        out[(b0 + bb) * NCLS + cc] = acc;
    }
}

extern "C" void kernel_launch(void* const* d_in, const int* in_sizes, int n_in,
                              void* d_out, int out_size)
{
    const float* mfcc0 = (const float*)d_in[0];
    const float* mfcc1 = (const float*)d_in[1];
    const float* mfcc2 = (const float*)d_in[2];
    const float* len0  = (const float*)d_in[3];
    const float* W_ih  = (const float*)d_in[4];
    const float* W_hh  = (const float*)d_in[5];
    const float* b_ih  = (const float*)d_in[6];
    const float* b_hh  = (const float*)d_in[7];
    const float* W_out = (const float*)d_in[8];
    const float* b_out = (const float*)d_in[9];
    float* out = (float*)d_out;

    cudaFuncSetAttribute(gru_onekernel,
                         cudaFuncAttributeMaxDynamicSharedMemorySize, SMEM_TOTAL);
    gru_onekernel<<<B_TOT / 2, 512, SMEM_TOTAL>>>(
        mfcc0, mfcc1, mfcc2, len0,
        W_ih, W_hh, b_ih, b_hh, W_out, b_out, out);
}